// round 2
// baseline (speedup 1.0000x reference)
#include <cuda_runtime.h>

#define DIMC 128
#define TM   64
#define TS   129   // padded smem stride (odd -> conflict-free column access)
#define NNODES 50000

// Scratch (no cudaMalloc allowed): h = relu(feats W_f^T + b_f), n = 1 + eps*h + sum
__device__ float g_h[(size_t)NNODES * DIMC];
__device__ float g_n[(size_t)NNODES * DIMC];

// C[M,128] = relu(A[M,128] @ W^T + bias); optionally also write n_init = 1 + eps*C
__global__ __launch_bounds__(256) void gemm_relu_kernel(
    const float* __restrict__ A, const float* __restrict__ W,
    const float* __restrict__ bias, float* __restrict__ out,
    float* __restrict__ n_init, const float* __restrict__ eps, int M)
{
    extern __shared__ float smem[];
    float* Ws = smem;              // [DIMC][TS]
    float* As = smem + DIMC * TS;  // [TM][TS]

    const int tid  = threadIdx.x;
    const int row0 = blockIdx.x * TM;

    // Load W (128x128, row-major [out][in]) into padded smem
    for (int i = tid; i < DIMC * DIMC; i += 256) {
        int r = i >> 7, c = i & 127;
        Ws[r * TS + c] = W[i];
    }
    // Load A tile (TM x 128)
    for (int i = tid; i < TM * DIMC; i += 256) {
        int r = i >> 7, c = i & 127;
        int gr = row0 + r;
        As[r * TS + c] = (gr < M) ? A[(size_t)gr * DIMC + c] : 0.0f;
    }
    __syncthreads();

    // Micro-tile: 4 rows x 8 cols per thread.
    const int tg = tid >> 4;       // 0..15
    const int tc = tid & 15;       // 0..15
    const int rr = tg * 4;

    float acc[4][8];
#pragma unroll
    for (int i = 0; i < 4; ++i)
#pragma unroll
        for (int j = 0; j < 8; ++j) acc[i][j] = 0.0f;

#pragma unroll 4
    for (int k = 0; k < DIMC; ++k) {
        float a[4], w[8];
#pragma unroll
        for (int i = 0; i < 4; ++i) a[i] = As[(rr + i) * TS + k];
#pragma unroll
        for (int j = 0; j < 8; ++j) w[j] = Ws[(tc + 16 * j) * TS + k];
#pragma unroll
        for (int i = 0; i < 4; ++i)
#pragma unroll
            for (int j = 0; j < 8; ++j) acc[i][j] = fmaf(a[i], w[j], acc[i][j]);
    }

    const float e = (n_init != nullptr) ? eps[0] : 0.0f;
#pragma unroll
    for (int i = 0; i < 4; ++i) {
        int gr = row0 + rr + i;
        if (gr >= M) continue;
#pragma unroll
        for (int j = 0; j < 8; ++j) {
            int c = tc + 16 * j;
            float v = fmaxf(acc[i][j] + bias[c], 0.0f);
            out[(size_t)gr * DIMC + c] = v;
            if (n_init) n_init[(size_t)gr * DIMC + c] = 1.0f + e * v;
        }
    }
}

// One warp per edge: gather h[src] (float4 per lane), atomicAdd(float4) to n[dst]
// NOTE: src/dst are int32 (JAX x64 disabled downcasts the int64 request).
__global__ __launch_bounds__(256) void scatter_kernel(
    const float* __restrict__ h, const int* __restrict__ src,
    const int* __restrict__ dst, float* __restrict__ nacc, int E)
{
    int gid  = blockIdx.x * blockDim.x + threadIdx.x;
    int e    = gid >> 5;
    int lane = gid & 31;
    if (e >= E) return;

    int s = src[e];
    int d = dst[e];

    float4 v = reinterpret_cast<const float4*>(h + (size_t)s * DIMC)[lane];
#if __CUDA_ARCH__ >= 900
    atomicAdd(reinterpret_cast<float4*>(nacc + (size_t)d * DIMC) + lane, v);
#else
    float* o = nacc + (size_t)d * DIMC + lane * 4;
    atomicAdd(o + 0, v.x); atomicAdd(o + 1, v.y);
    atomicAdd(o + 2, v.z); atomicAdd(o + 3, v.w);
#endif
}

extern "C" void kernel_launch(void* const* d_in, const int* in_sizes, int n_in,
                              void* d_out, int out_size)
{
    const float* feats = (const float*)d_in[0];
    const int*   src   = (const int*)d_in[1];
    const int*   dst   = (const int*)d_in[2];
    const float* W_f   = (const float*)d_in[3];
    const float* b_f   = (const float*)d_in[4];
    const float* W_phy = (const float*)d_in[5];
    const float* b_phy = (const float*)d_in[6];
    const float* eps   = (const float*)d_in[7];
    float*       out   = (float*)d_out;

    const int M = in_sizes[0] / DIMC;   // 50000
    const int E = in_sizes[1];          // 625000

    float *h_ptr, *n_ptr;
    cudaGetSymbolAddress((void**)&h_ptr, g_h);
    cudaGetSymbolAddress((void**)&n_ptr, g_n);

    const size_t smem = (size_t)(DIMC + TM) * TS * sizeof(float);  // ~99 KB
    cudaFuncSetAttribute(gemm_relu_kernel,
                         cudaFuncAttributeMaxDynamicSharedMemorySize, (int)smem);

    const int gblocks = (M + TM - 1) / TM;

    // h = relu(feats W_f^T + b_f); n = 1 + eps*h
    gemm_relu_kernel<<<gblocks, 256, smem>>>(feats, W_f, b_f, h_ptr, n_ptr, eps, M);

    // n += sum_{edges} h[src] at dst
    long long total_threads = (long long)E * 32;
    int sblocks = (int)((total_threads + 255) / 256);
    scatter_kernel<<<sblocks, 256>>>(h_ptr, src, dst, n_ptr, E);

    // out = relu(n W_phy^T + b_phy)
    gemm_relu_kernel<<<gblocks, 256, smem>>>(n_ptr, W_phy, b_phy, out, nullptr, nullptr, M);
}

// round 3
// speedup vs baseline: 1.1193x; 1.1193x over previous
#include <cuda_runtime.h>

#define DIMC 128
#define TM   64
#define SA   129   // As stride (odd -> conflict-free broadcast column reads)
#define SWT  130   // W^T stride (even, 8B-aligned rows for LDS.64; 2-way store conflict only)
#define NNODES 50000

// Scratch (no cudaMalloc allowed)
__device__ float g_h[(size_t)NNODES * DIMC];
__device__ float g_n[(size_t)NNODES * DIMC];

#define FMA_F32X2(d, a, b) \
    asm("fma.rn.f32x2 %0, %1, %2, %0;" : "+l"(d) : "l"(a), "l"(b))
#define PACK_DUP_F32X2(d, x) \
    asm("mov.b64 %0, {%1, %1};" : "=l"(d) : "f"(x))
#define UNPACK_F32X2(lo, hi, v) \
    asm("mov.b64 {%0, %1}, %2;" : "=f"(lo), "=f"(hi) : "l"(v))

// C[M,128] = relu(A[M,128] @ W^T + bias); optionally also n_init = 1 + eps*C
__global__ __launch_bounds__(256) void gemm_relu_kernel(
    const float* __restrict__ A, const float* __restrict__ W,
    const float* __restrict__ bias, float* __restrict__ out,
    float* __restrict__ n_init, const float* __restrict__ eps, int M)
{
    extern __shared__ float smem[];
    float* Wt = smem;               // W^T: [k=128][SWT]  (Wt[k*SWT + col] = W[col][k])
    float* As = smem + DIMC * SWT;  // A tile: [TM][SA]

    const int tid  = threadIdx.x;
    const int row0 = blockIdx.x * TM;

    // Load W (row-major [out_col][k]) transposed into smem.
    // LDG coalesced (consecutive tid -> consecutive k); STS 2-way conflict (one-time).
    for (int i = tid; i < DIMC * DIMC; i += 256) {
        int col = i >> 7, k = i & 127;
        Wt[k * SWT + col] = W[i];
    }
    // Load A tile (natural layout), coalesced LDG, conflict-free STS.
    for (int i = tid; i < TM * DIMC; i += 256) {
        int r = i >> 7, c = i & 127;
        int gr = row0 + r;
        As[r * SA + c] = (gr < M) ? A[(size_t)gr * DIMC + c] : 0.0f;
    }
    __syncthreads();

    // Micro-tile: 4 rows x 8 cols per thread; cols packed as 4 float2 pairs.
    // rows: rr..rr+3; col pairs: (2*tc + 32*j, +1) for j=0..3
    const int tg = tid >> 4;       // 0..15
    const int tc = tid & 15;       // 0..15
    const int rr = tg * 4;

    unsigned long long acc[4][4];
#pragma unroll
    for (int i = 0; i < 4; ++i)
#pragma unroll
        for (int j = 0; j < 4; ++j) acc[i][j] = 0ULL;

#pragma unroll 8
    for (int k = 0; k < DIMC; ++k) {
        // a: 4 scalar broadcast LDS (conflict-free), replicated into f32x2
        unsigned long long aP[4];
#pragma unroll
        for (int i = 0; i < 4; ++i) {
            float av = As[(rr + i) * SA + k];
            PACK_DUP_F32X2(aP[i], av);
        }
        // w: 4 x LDS.64 — 16 distinct contiguous float2 per warp (broadcast dedup) -> 1 wf each
        unsigned long long wv[4];
#pragma unroll
        for (int j = 0; j < 4; ++j)
            wv[j] = *reinterpret_cast<const unsigned long long*>(
                        &Wt[k * SWT + 2 * tc + 32 * j]);
        // 16 packed FFMA2 = 32 scalar FMA
#pragma unroll
        for (int i = 0; i < 4; ++i)
#pragma unroll
            for (int j = 0; j < 4; ++j)
                FMA_F32X2(acc[i][j], aP[i], wv[j]);
    }

    const float e = (n_init != nullptr) ? eps[0] : 0.0f;
#pragma unroll
    for (int i = 0; i < 4; ++i) {
        int gr = row0 + rr + i;
        if (gr >= M) continue;
#pragma unroll
        for (int j = 0; j < 4; ++j) {
            int c = 2 * tc + 32 * j;
            float lo, hi;
            UNPACK_F32X2(lo, hi, acc[i][j]);
            float v0 = fmaxf(lo + bias[c], 0.0f);
            float v1 = fmaxf(hi + bias[c + 1], 0.0f);
            *reinterpret_cast<float2*>(&out[(size_t)gr * DIMC + c])
                = make_float2(v0, v1);
            if (n_init)
                *reinterpret_cast<float2*>(&n_init[(size_t)gr * DIMC + c])
                    = make_float2(1.0f + e * v0, 1.0f + e * v1);
        }
    }
}

// One warp per edge: gather h[src] (float4 per lane), atomicAdd(float4) to n[dst]
// src/dst are int32 (JAX x64 disabled).
__global__ __launch_bounds__(256) void scatter_kernel(
    const float* __restrict__ h, const int* __restrict__ src,
    const int* __restrict__ dst, float* __restrict__ nacc, int E)
{
    int gid  = blockIdx.x * blockDim.x + threadIdx.x;
    int e    = gid >> 5;
    int lane = gid & 31;
    if (e >= E) return;

    int s = src[e];
    int d = dst[e];

    float4 v = reinterpret_cast<const float4*>(h + (size_t)s * DIMC)[lane];
    atomicAdd(reinterpret_cast<float4*>(nacc + (size_t)d * DIMC) + lane, v);
}

extern "C" void kernel_launch(void* const* d_in, const int* in_sizes, int n_in,
                              void* d_out, int out_size)
{
    const float* feats = (const float*)d_in[0];
    const int*   src   = (const int*)d_in[1];
    const int*   dst   = (const int*)d_in[2];
    const float* W_f   = (const float*)d_in[3];
    const float* b_f   = (const float*)d_in[4];
    const float* W_phy = (const float*)d_in[5];
    const float* b_phy = (const float*)d_in[6];
    const float* eps   = (const float*)d_in[7];
    float*       out   = (float*)d_out;

    const int M = in_sizes[0] / DIMC;   // 50000
    const int E = in_sizes[1];          // 625000

    float *h_ptr, *n_ptr;
    cudaGetSymbolAddress((void**)&h_ptr, g_h);
    cudaGetSymbolAddress((void**)&n_ptr, g_n);

    const size_t smem = (size_t)(DIMC * SWT + TM * SA) * sizeof(float);  // 99,584 B
    cudaFuncSetAttribute(gemm_relu_kernel,
                         cudaFuncAttributeMaxDynamicSharedMemorySize, (int)smem);

    const int gblocks = (M + TM - 1) / TM;

    // h = relu(feats W_f^T + b_f); n = 1 + eps*h
    gemm_relu_kernel<<<gblocks, 256, smem>>>(feats, W_f, b_f, h_ptr, n_ptr, eps, M);

    // n += sum_{edges} h[src] at dst
    long long total_threads = (long long)E * 32;
    int sblocks = (int)((total_threads + 255) / 256);
    scatter_kernel<<<sblocks, 256>>>(h_ptr, src, dst, n_ptr, E);

    // out = relu(n W_phy^T + b_phy)
    gemm_relu_kernel<<<gblocks, 256, smem>>>(n_ptr, W_phy, b_phy, out, nullptr, nullptr, M);
}